// round 2
// baseline (speedup 1.0000x reference)
#include <cuda_runtime.h>
#include <cstdint>

#define N_NODES 100000
#define N_EDGES_MAX 3200000
#define IN_C 64
#define HID_C 64
#define OUT_C 32

// Scratch (static __device__ arrays per harness rules)
__device__ __align__(16) float g_sum1[(size_t)N_NODES * HID_C];   // 25.6 MB
__device__ __align__(16) float g_h   [(size_t)N_NODES * HID_C];   // 25.6 MB
__device__ __align__(16) float g_p2  [(size_t)N_NODES * OUT_C];   // 12.8 MB
__device__ __align__(16) float g_sum2[(size_t)N_NODES * OUT_C];   // 12.8 MB
__device__ __align__(16) float g_deg [N_NODES];                   // 0.4 MB
__device__ __align__(16) int   g_eidx[(size_t)2 * N_EDGES_MAX];   // 25.6 MB
__device__ int g_is64;

// ---------------------------------------------------------------------------
// Detect whether the edge buffer is int64 or int32.
// If int64 (values < 2^31), every odd 32-bit word is 0.
// ---------------------------------------------------------------------------
__global__ void detect_dtype_kernel(const int* __restrict__ ei32) {
    __shared__ int nz;
    if (threadIdx.x == 0) nz = 0;
    __syncthreads();
    // sample 8192 odd words
    int any = 0;
    for (int i = threadIdx.x; i < 8192; i += blockDim.x)
        if (ei32[2 * i + 1] != 0) any = 1;
    if (any) atomicOr(&nz, 1);
    __syncthreads();
    if (threadIdx.x == 0) g_is64 = (nz == 0) ? 1 : 0;
}

// ---------------------------------------------------------------------------
// Normalize edge indices to int32 in g_eidx (layout [2*E], same as input).
// ---------------------------------------------------------------------------
__global__ void convert_edges_kernel(const void* __restrict__ ei, int total) {
    int i = blockIdx.x * blockDim.x + threadIdx.x;
    if (i >= total) return;
    if (g_is64) g_eidx[i] = (int)((const long long*)ei)[i];
    else        g_eidx[i] = ((const int*)ei)[i];
}

// ---------------------------------------------------------------------------
// Scatter 1: per edge, sum1[dst] += x[src] (64 floats), deg[dst] += 1
// 16 lanes per edge, each lane handles a float4 (16B vector reduction).
// ---------------------------------------------------------------------------
__global__ void scatter1_kernel(const float* __restrict__ x, int E) {
    unsigned tid = blockIdx.x * blockDim.x + threadIdx.x;
    unsigned e = tid >> 4;
    if (e >= (unsigned)E) return;
    int lane = tid & 15;
    int s = g_eidx[e];
    int d = g_eidx[(size_t)E + e];
    float4 v = ((const float4*)(x + (size_t)s * 64))[lane];
    atomicAdd(((float4*)(g_sum1 + (size_t)d * 64)) + lane, v);
    if (lane == 0) atomicAdd(g_deg + d, 1.0f);
}

// ---------------------------------------------------------------------------
// Scatter 2: per edge, sum2[dst] += p2[src] (32 floats). 8 lanes per edge.
// ---------------------------------------------------------------------------
__global__ void scatter2_kernel(int E) {
    unsigned tid = blockIdx.x * blockDim.x + threadIdx.x;
    unsigned e = tid >> 3;
    if (e >= (unsigned)E) return;
    int lane = tid & 7;
    int s = g_eidx[e];
    int d = g_eidx[(size_t)E + e];
    float4 v = ((const float4*)(g_p2 + (size_t)s * 32))[lane];
    atomicAdd(((float4*)(g_sum2 + (size_t)d * 32)) + lane, v);
}

// ---------------------------------------------------------------------------
// GEMM1: h[n, 64] = relu( (sum1[n,:]/max(deg,1)) @ W1l + x[n,:] @ W1r + b1l )
// Tile: 128 nodes x 64 cols per block (256 threads). Thread tile 8x4.
// A staged transposed in smem [k][node]; B staged [k][j]. Two K=64 passes.
// ---------------------------------------------------------------------------
__global__ __launch_bounds__(256) void gemm1_kernel(
    const float* __restrict__ x,  const float* __restrict__ W1l,
    const float* __restrict__ b1l, const float* __restrict__ W1r) {
    __shared__ float sA[64 * 128];  // 32 KB, [k][node]
    __shared__ float sB[64 * 64];   // 16 KB, [k][j]
    int t  = threadIdx.x;
    int cg = t & 15;   // col group: cols 4*cg .. 4*cg+3
    int ng = t >> 4;   // node group: nodes 8*ng .. 8*ng+7
    int nodeBase = blockIdx.x * 128;

    float acc[8][4];
#pragma unroll
    for (int m = 0; m < 8; m++)
#pragma unroll
        for (int c = 0; c < 4; c++) acc[m][c] = 0.0f;

    for (int pass = 0; pass < 2; ++pass) {
        const float* A = pass ? x   : g_sum1;
        const float* B = pass ? W1r : W1l;
        __syncthreads();
        // Stage B: 64*64 floats = 1024 float4 / 256 threads
#pragma unroll
        for (int i = 0; i < 4; i++) {
            int f4 = t + i * 256;
            ((float4*)sB)[f4] = ((const float4*)B)[f4];
        }
        // Stage A transposed: 128 nodes * 64 k = 2048 float4 / 256 threads
#pragma unroll
        for (int i = 0; i < 8; i++) {
            int f4 = t + i * 256;          // 0..2047
            int node = f4 >> 4;            // 16 float4 per node row
            int kq   = f4 & 15;
            int gnode = nodeBase + node;
            float4 v = make_float4(0.f, 0.f, 0.f, 0.f);
            if (gnode < N_NODES) {
                v = ((const float4*)(A + (size_t)gnode * 64))[kq];
                if (pass == 0) {
                    float invd = 1.0f / fmaxf(g_deg[gnode], 1.0f);
                    v.x *= invd; v.y *= invd; v.z *= invd; v.w *= invd;
                }
            }
            int k0 = kq * 4;
            sA[(k0 + 0) * 128 + node] = v.x;
            sA[(k0 + 1) * 128 + node] = v.y;
            sA[(k0 + 2) * 128 + node] = v.z;
            sA[(k0 + 3) * 128 + node] = v.w;
        }
        __syncthreads();
#pragma unroll 8
        for (int k = 0; k < 64; k++) {
            float4 b  = ((const float4*)(sB + k * 64))[cg];
            float4 a0 = ((const float4*)(sA + k * 128))[ng * 2];
            float4 a1 = ((const float4*)(sA + k * 128))[ng * 2 + 1];
            float am[8] = {a0.x, a0.y, a0.z, a0.w, a1.x, a1.y, a1.z, a1.w};
#pragma unroll
            for (int m = 0; m < 8; m++) {
                acc[m][0] = fmaf(am[m], b.x, acc[m][0]);
                acc[m][1] = fmaf(am[m], b.y, acc[m][1]);
                acc[m][2] = fmaf(am[m], b.z, acc[m][2]);
                acc[m][3] = fmaf(am[m], b.w, acc[m][3]);
            }
        }
    }
    float4 bias = ((const float4*)b1l)[cg];
#pragma unroll
    for (int m = 0; m < 8; m++) {
        int node = nodeBase + ng * 8 + m;
        if (node < N_NODES) {
            float4 r;
            r.x = fmaxf(acc[m][0] + bias.x, 0.f);
            r.y = fmaxf(acc[m][1] + bias.y, 0.f);
            r.z = fmaxf(acc[m][2] + bias.z, 0.f);
            r.w = fmaxf(acc[m][3] + bias.w, 0.f);
            ((float4*)(g_h + (size_t)node * 64))[cg] = r;
        }
    }
}

// ---------------------------------------------------------------------------
// GEMM2: p2[n,0:32] = h @ W2l ; out[n,0:32] = h @ W2r + b2l  (combined N=64)
// ---------------------------------------------------------------------------
__global__ __launch_bounds__(256) void gemm2_kernel(
    const float* __restrict__ W2l, const float* __restrict__ b2l,
    const float* __restrict__ W2r, float* __restrict__ out) {
    __shared__ float sA[64 * 128];  // [k][node]
    __shared__ float sB[64 * 64];   // [k][j], j<32: W2l, j>=32: W2r
    int t  = threadIdx.x;
    int cg = t & 15;
    int ng = t >> 4;
    int nodeBase = blockIdx.x * 128;

    float acc[8][4];
#pragma unroll
    for (int m = 0; m < 8; m++)
#pragma unroll
        for (int c = 0; c < 4; c++) acc[m][c] = 0.0f;

    // Stage combined B: 1024 float4
#pragma unroll
    for (int i = 0; i < 4; i++) {
        int f4 = t + i * 256;
        int k  = f4 >> 4;
        int jq = f4 & 15;
        float4 v = (jq < 8) ? ((const float4*)W2l)[k * 8 + jq]
                            : ((const float4*)W2r)[k * 8 + (jq - 8)];
        ((float4*)sB)[f4] = v;
    }
    // Stage A = h, transposed
#pragma unroll
    for (int i = 0; i < 8; i++) {
        int f4 = t + i * 256;
        int node = f4 >> 4;
        int kq   = f4 & 15;
        int gnode = nodeBase + node;
        float4 v = make_float4(0.f, 0.f, 0.f, 0.f);
        if (gnode < N_NODES)
            v = ((const float4*)(g_h + (size_t)gnode * 64))[kq];
        int k0 = kq * 4;
        sA[(k0 + 0) * 128 + node] = v.x;
        sA[(k0 + 1) * 128 + node] = v.y;
        sA[(k0 + 2) * 128 + node] = v.z;
        sA[(k0 + 3) * 128 + node] = v.w;
    }
    __syncthreads();
#pragma unroll 8
    for (int k = 0; k < 64; k++) {
        float4 b  = ((const float4*)(sB + k * 64))[cg];
        float4 a0 = ((const float4*)(sA + k * 128))[ng * 2];
        float4 a1 = ((const float4*)(sA + k * 128))[ng * 2 + 1];
        float am[8] = {a0.x, a0.y, a0.z, a0.w, a1.x, a1.y, a1.z, a1.w};
#pragma unroll
        for (int m = 0; m < 8; m++) {
            acc[m][0] = fmaf(am[m], b.x, acc[m][0]);
            acc[m][1] = fmaf(am[m], b.y, acc[m][1]);
            acc[m][2] = fmaf(am[m], b.z, acc[m][2]);
            acc[m][3] = fmaf(am[m], b.w, acc[m][3]);
        }
    }
#pragma unroll
    for (int m = 0; m < 8; m++) {
        int node = nodeBase + ng * 8 + m;
        if (node < N_NODES) {
            if (cg < 8) {  // p2 = h @ W2l (no bias)
                float4 r = make_float4(acc[m][0], acc[m][1], acc[m][2], acc[m][3]);
                ((float4*)(g_p2 + (size_t)node * 32))[cg] = r;
            } else {       // out partial = h @ W2r + b2l
                float4 bias = ((const float4*)b2l)[cg - 8];
                float4 r;
                r.x = acc[m][0] + bias.x;
                r.y = acc[m][1] + bias.y;
                r.z = acc[m][2] + bias.z;
                r.w = acc[m][3] + bias.w;
                ((float4*)(out + (size_t)node * 32))[cg - 8] = r;
            }
        }
    }
}

// ---------------------------------------------------------------------------
// Final: out[n, :] += sum2[n, :] / max(deg[n], 1)
// ---------------------------------------------------------------------------
__global__ void final_add_kernel(float* __restrict__ out) {
    unsigned i = blockIdx.x * blockDim.x + threadIdx.x;  // over N*8 float4s
    if (i >= (unsigned)(N_NODES * 8)) return;
    int node = i >> 3;
    float invd = 1.0f / fmaxf(g_deg[node], 1.0f);
    float4 s = ((const float4*)g_sum2)[i];
    float4 o = ((float4*)out)[i];
    o.x = fmaf(s.x, invd, o.x);
    o.y = fmaf(s.y, invd, o.y);
    o.z = fmaf(s.z, invd, o.z);
    o.w = fmaf(s.w, invd, o.w);
    ((float4*)out)[i] = o;
}

extern "C" void kernel_launch(void* const* d_in, const int* in_sizes, int n_in,
                              void* d_out, int out_size) {
    const float* x   = (const float*)d_in[0];
    const void*  ei  = d_in[1];
    const float* W1l = (const float*)d_in[2];
    const float* b1l = (const float*)d_in[3];
    const float* W1r = (const float*)d_in[4];
    const float* W2l = (const float*)d_in[5];
    const float* b2l = (const float*)d_in[6];
    const float* W2r = (const float*)d_in[7];
    float* out = (float*)d_out;
    int E = in_sizes[1] / 2;   // element count is 2*E for either dtype

    void *p_sum1, *p_sum2, *p_deg;
    cudaGetSymbolAddress(&p_sum1, g_sum1);
    cudaGetSymbolAddress(&p_sum2, g_sum2);
    cudaGetSymbolAddress(&p_deg,  g_deg);

    cudaMemsetAsync(p_sum1, 0, (size_t)N_NODES * HID_C * sizeof(float), 0);
    cudaMemsetAsync(p_sum2, 0, (size_t)N_NODES * OUT_C * sizeof(float), 0);
    cudaMemsetAsync(p_deg,  0, (size_t)N_NODES * sizeof(float), 0);

    // dtype detect + normalize edges to int32
    detect_dtype_kernel<<<1, 256>>>((const int*)ei);
    {
        int total = 2 * E;
        convert_edges_kernel<<<(total + 255) / 256, 256>>>(ei, total);
    }
    {   // scatter1: E edges * 16 lanes
        unsigned total = (unsigned)E * 16u;
        scatter1_kernel<<<(total + 255) / 256, 256>>>(x, E);
    }
    {   // gemm1
        int blocks = (N_NODES + 127) / 128;
        gemm1_kernel<<<blocks, 256>>>(x, W1l, b1l, W1r);
    }
    {   // gemm2
        int blocks = (N_NODES + 127) / 128;
        gemm2_kernel<<<blocks, 256>>>(W2l, b2l, W2r, out);
    }
    {   // scatter2: E edges * 8 lanes
        unsigned total = (unsigned)E * 8u;
        scatter2_kernel<<<(total + 255) / 256, 256>>>(E);
    }
    {   // final add
        unsigned total = N_NODES * 8;
        final_add_kernel<<<(total + 255) / 256, 256>>>(out);
    }
}